// round 9
// baseline (speedup 1.0000x reference)
#include <cuda_runtime.h>
#include <cstdint>

#define NG   64                 // n
#define NN   (NG * NG)          // 4096 = N
#define SDIM (3 * NN)           // 12288
#define LRF  0.001f

__device__ float g_dx;

// dx = 10 * max(c) * sqrt(2). Single block, 16KB read (L2-resident after wave 1).
__global__ __launch_bounds__(256)
void max_kernel(const float* __restrict__ c)
{
    __shared__ float s[256];
    float m = 0.0f;                                  // c ~ uniform[0,1): positive
    for (int i = threadIdx.x; i < NN; i += 256) m = fmaxf(m, c[i]);
    s[threadIdx.x] = m;
    __syncthreads();
    #pragma unroll
    for (int st = 128; st > 0; st >>= 1) {
        if (threadIdx.x < st) s[threadIdx.x] = fmaxf(s[threadIdx.x], s[threadIdx.x + st]);
        __syncthreads();
    }
    if (threadIdx.x == 0) g_dx = 10.0f * s[0] * 1.41421356237309515f;
}

// Rare path: compute the float4 at [row R, cols col0..col0+3].
__device__ __noinline__
float4 value_f4(int band, int r, int col0,
                const float* __restrict__ c,  const float* __restrict__ kp,
                const float* __restrict__ kx_in, const float* __restrict__ ky_in,
                const float* __restrict__ dk)
{
    const float dx = g_dx;
    const int ii = r & (NG - 1);
    const int i  = r >> 6;
    const int t  = ii * NG + i;                  // transpose-flatten index

    const bool has_pn = (r < NN - NG);
    const bool has_mn = (r >= NG);
    const bool has_p1 = (ii != NG - 1);
    const bool has_m1 = (ii != 0);

    const float cd = c[t] / dx;

    const float kxr     = kx_in[t] - LRF * dk[t];
    const float nxinv_r = 1.0f / (1.0f + kxr * 0.5f);
    const float Nxp_r   = 1.0f - kxr * 0.5f;

    const float kyr     = ky_in[t] - LRF * dk[t];
    const float nyinv_r = 1.0f / (1.0f + kyr * 0.5f);
    const float Nyp_r   = 1.0f - kyr * 0.5f;

    float c_pn = 0.f, c_mn = 0.f, c_p1 = 0.f;
    float nxinv_pn = 0.f, Nxp_pn = 0.f, nyinv_p1 = 0.f, Nyp_p1 = 0.f;
    if (has_pn) {
        c_pn = c[t + 1];
        const float kxp = kx_in[t + 1] - LRF * dk[t + 1];
        nxinv_pn = 1.0f / (1.0f + kxp * 0.5f);
        Nxp_pn   = 1.0f - kxp * 0.5f;
    }
    if (has_mn) c_mn = c[t - 1];
    if (has_p1) {
        c_p1 = c[t + NG];
        const float kyp = ky_in[t + NG] - LRF * dk[t + NG];
        nyinv_p1 = 1.0f / (1.0f + kyp * 0.5f);
        Nyp_p1   = 1.0f - kyp * 0.5f;
    }
    const float cpd = c_p1 / dx;

    float4 v = make_float4(0.f, 0.f, 0.f, 0.f);
    float* vp = (float*)&v;
    #define PUT(COL, VAL) do { int _d = (COL) - col0; \
        if ((unsigned)_d < 4u) vp[_d] = (VAL); } while (0)

    if (band == 0) {
        const float kpv  = kp[ii];
        const float minv = 1.0f / (1.0f - kpv * 0.5f);
        const float Mp   = 1.0f + kpv * 0.5f;

        float txss = -cd * cd * nxinv_r;
        if (has_pn) txss += -cd * cd * nxinv_pn;
        float tyss = -cd * cd * nyinv_r;
        if (has_p1) tyss += -cpd * cpd * nyinv_p1;

        if (has_mn) PUT(r - NG, minv * cd * (c_mn / dx) * nxinv_r);
        if (has_m1) PUT(r - 1,  minv * cd * cd * nyinv_r);
        PUT(r, minv * Mp + minv * (txss + tyss));
        if (has_p1) PUT(r + 1,  minv * cpd * cpd * nyinv_p1);
        if (has_pn) PUT(r + NG, minv * cd * (c_pn / dx) * nxinv_pn);

        PUT(NN + r, minv * cd * nxinv_r * Nxp_r);
        if (has_pn) PUT(NN + r + NG, -minv * cd * nxinv_pn * Nxp_pn);

        PUT(2 * NN + r, minv * cd * nyinv_r * Nyp_r);
        if (has_p1) PUT(2 * NN + r + 1, -minv * cpd * nyinv_p1 * Nyp_p1);
    } else if (band == 1) {
        if (has_mn) PUT(r - NG, nxinv_r * (c_mn / dx));
        PUT(r, -nxinv_r * cd);
        PUT(NN + r, nxinv_r * Nxp_r);
    } else {
        if (has_m1) PUT(r - 1, nyinv_r * cd);
        PUT(r, -nyinv_r * cd);
        PUT(2 * NN + r, nyinv_r * Nyp_r);
    }
    #undef PUT
    return v;
}

// One block per output row R. 256 threads x 12 float4 = 12288 floats/row.
// Per (warp,k) iteration the warp covers 128 contiguous columns; the band
// test is warp-uniform, so the common path is a branch + STG.128 of zeros.
__global__ __launch_bounds__(256)
void fill_kernel(const float* __restrict__ c,
                 const float* __restrict__ kp,
                 const float* __restrict__ kx_in,
                 const float* __restrict__ ky_in,
                 const float* __restrict__ dk,
                 float* __restrict__ out)
{
    const int R = blockIdx.x;
    float4* rowp = (float4*)(out + (size_t)R * SDIM);

    int band, r;
    if (R < NN)          { band = 0; r = R; }
    else if (R < 2 * NN) { band = 1; r = R - NN; }
    else                 { band = 2; r = R - 2 * NN; }

    // Inclusive nonzero-column intervals for this row (sentinel = empty).
    int i1lo, i1hi, i2lo, i2hi, i3lo, i3hi;
    if (band == 0) {
        i1lo = r - NG;      i1hi = r + NG;
        i2lo = NN + r;      i2hi = NN + r + NG;
        i3lo = 2 * NN + r;  i3hi = 2 * NN + r + 1;
    } else if (band == 1) {
        i1lo = r - NG;      i1hi = r;
        i2lo = NN + r;      i2hi = NN + r;
        i3lo = 1 << 30;     i3hi = -(1 << 30);
    } else {
        i1lo = r - 1;       i1hi = r;
        i2lo = 2 * NN + r;  i2hi = 2 * NN + r;
        i3lo = 1 << 30;     i3hi = -(1 << 30);
    }

    const int tid  = threadIdx.x;
    const int wcol = (tid >> 5) << 7;            // warp's column offset within a 1024-col chunk
    const float4 z = make_float4(0.f, 0.f, 0.f, 0.f);

    #pragma unroll
    for (int k = 0; k < 12; k++) {
        const int f4  = k * 256 + tid;           // float4 index in row
        const int wlo = k * 1024 + wcol;         // warp-chunk columns [wlo, wlo+128)
        const int whi = wlo + 127;

        // warp-uniform band test
        if ((whi >= i1lo && wlo <= i1hi) ||
            (whi >= i2lo && wlo <= i2hi) ||
            (whi >= i3lo && wlo <= i3hi)) {
            rowp[f4] = value_f4(band, r, f4 * 4, c, kp, kx_in, ky_in, dk);
        } else {
            rowp[f4] = z;
        }
    }
}

extern "C" void kernel_launch(void* const* d_in, const int* in_sizes, int n_in,
                              void* d_out, int out_size)
{
    const float* c  = (const float*)d_in[0];
    const float* kp = (const float*)d_in[1];
    const float* kx = (const float*)d_in[2];
    const float* ky = (const float*)d_in[3];
    const float* dk = (const float*)d_in[4];
    float* out = (float*)d_out;

    max_kernel<<<1, 256>>>(c);
    fill_kernel<<<SDIM, 256>>>(c, kp, kx, ky, dk, out);
}

// round 10
// speedup vs baseline: 1.0115x; 1.0115x over previous
#include <cuda_runtime.h>
#include <cstdint>

#define NG   64                 // n
#define NN   (NG * NG)          // 4096 = N
#define SDIM (3 * NN)           // 12288
#define F4PR (SDIM / 4)         // 3072 float4 per row
#define CHPR (SDIM / 128)       // 96 chunks of 128 floats per row
#define LRF  0.001f

__device__ float g_dx;

// dx = 10 * max(c) * sqrt(2). Single block, 16KB read.
__global__ __launch_bounds__(256)
void max_kernel(const float* __restrict__ c)
{
    __shared__ float s[256];
    const float4* c4 = (const float4*)c;
    float m = 0.0f;                                  // c ~ uniform[0,1): positive
    #pragma unroll
    for (int k = 0; k < 4; k++) {
        float4 v = c4[k * 256 + threadIdx.x];
        m = fmaxf(m, fmaxf(fmaxf(v.x, v.y), fmaxf(v.z, v.w)));
    }
    s[threadIdx.x] = m;
    __syncthreads();
    #pragma unroll
    for (int st = 128; st > 0; st >>= 1) {
        if (threadIdx.x < st) s[threadIdx.x] = fmaxf(s[threadIdx.x], s[threadIdx.x + st]);
        __syncthreads();
    }
    if (threadIdx.x == 0) g_dx = 10.0f * s[0] * 1.41421356237309515f;
}

// Rare path (inline): the float4 at [band-row r, cols col0..col0+3].
__device__ __forceinline__
float4 value_f4(int band, int r, int col0,
                const float* __restrict__ c,  const float* __restrict__ kp,
                const float* __restrict__ kx_in, const float* __restrict__ ky_in,
                const float* __restrict__ dk)
{
    const float dx = g_dx;
    const int ii = r & (NG - 1);
    const int i  = r >> 6;
    const int t  = ii * NG + i;                  // transpose-flatten index

    const bool has_pn = (r < NN - NG);
    const bool has_mn = (r >= NG);
    const bool has_p1 = (ii != NG - 1);
    const bool has_m1 = (ii != 0);

    const float cd = c[t] / dx;

    const float kxr     = kx_in[t] - LRF * dk[t];
    const float nxinv_r = 1.0f / (1.0f + kxr * 0.5f);
    const float Nxp_r   = 1.0f - kxr * 0.5f;

    const float kyr     = ky_in[t] - LRF * dk[t];
    const float nyinv_r = 1.0f / (1.0f + kyr * 0.5f);
    const float Nyp_r   = 1.0f - kyr * 0.5f;

    float c_pn = 0.f, c_mn = 0.f, c_p1 = 0.f;
    float nxinv_pn = 0.f, Nxp_pn = 0.f, nyinv_p1 = 0.f, Nyp_p1 = 0.f;
    if (has_pn) {
        c_pn = c[t + 1];
        const float kxp = kx_in[t + 1] - LRF * dk[t + 1];
        nxinv_pn = 1.0f / (1.0f + kxp * 0.5f);
        Nxp_pn   = 1.0f - kxp * 0.5f;
    }
    if (has_mn) c_mn = c[t - 1];
    if (has_p1) {
        c_p1 = c[t + NG];
        const float kyp = ky_in[t + NG] - LRF * dk[t + NG];
        nyinv_p1 = 1.0f / (1.0f + kyp * 0.5f);
        Nyp_p1   = 1.0f - kyp * 0.5f;
    }
    const float cpd = c_p1 / dx;

    float4 v = make_float4(0.f, 0.f, 0.f, 0.f);
    float* vp = (float*)&v;
    #define PUT(COL, VAL) do { int _d = (COL) - col0; \
        if ((unsigned)_d < 4u) vp[_d] = (VAL); } while (0)

    if (band == 0) {
        const float kpv  = kp[ii];
        const float minv = 1.0f / (1.0f - kpv * 0.5f);
        const float Mp   = 1.0f + kpv * 0.5f;

        float txss = -cd * cd * nxinv_r;
        if (has_pn) txss += -cd * cd * nxinv_pn;
        float tyss = -cd * cd * nyinv_r;
        if (has_p1) tyss += -cpd * cpd * nyinv_p1;

        if (has_mn) PUT(r - NG, minv * cd * (c_mn / dx) * nxinv_r);
        if (has_m1) PUT(r - 1,  minv * cd * cd * nyinv_r);
        PUT(r, minv * Mp + minv * (txss + tyss));
        if (has_p1) PUT(r + 1,  minv * cpd * cpd * nyinv_p1);
        if (has_pn) PUT(r + NG, minv * cd * (c_pn / dx) * nxinv_pn);

        PUT(NN + r, minv * cd * nxinv_r * Nxp_r);
        if (has_pn) PUT(NN + r + NG, -minv * cd * nxinv_pn * Nxp_pn);

        PUT(2 * NN + r, minv * cd * nyinv_r * Nyp_r);
        if (has_p1) PUT(2 * NN + r + 1, -minv * cpd * nyinv_p1 * Nyp_p1);
    } else if (band == 1) {
        if (has_mn) PUT(r - NG, nxinv_r * (c_mn / dx));
        PUT(r, -nxinv_r * cd);
        PUT(NN + r, nxinv_r * Nxp_r);
    } else {
        if (has_m1) PUT(r - 1, nyinv_r * cd);
        PUT(r, -nyinv_r * cd);
        PUT(2 * NN + r, nyinv_r * Nyp_r);
    }
    #undef PUT
    return v;
}

// Persistent fill: 608 CTAs (4/SM), warp-grid-stride over 128-float chunks.
// Common path per warp-iteration: uniform interval test + one STG.128/lane.
__global__ __launch_bounds__(256, 4)
void fill_kernel(const float* __restrict__ c,
                 const float* __restrict__ kp,
                 const float* __restrict__ kx_in,
                 const float* __restrict__ ky_in,
                 const float* __restrict__ dk,
                 float* __restrict__ out)
{
    const int warps_total = (gridDim.x * blockDim.x) >> 5;       // e.g. 4864
    const int wid  = (blockIdx.x * blockDim.x + threadIdx.x) >> 5;
    const int lane = threadIdx.x & 31;

    const int CHUNKS = SDIM * CHPR;              // 1,179,648
    // carried counters: chunk -> (row, cc); stride decomposition
    const int d_row = warps_total / CHPR;
    const int d_cc  = warps_total % CHPR;

    int chunk = wid;
    int row   = chunk / CHPR;
    int cc    = chunk - row * CHPR;              // chunk-col within row

    const float4 z = make_float4(0.f, 0.f, 0.f, 0.f);

    while (chunk < CHUNKS) {
        const int band    = row >> 12;
        const int r       = row & (NN - 1);
        const int colbase = cc << 7;             // first column of this chunk

        // warp-uniform hit test (colbase .. colbase+127 vs nonzero intervals)
        bool hit;
        if (band == 0) {
            hit = (colbase >= r - NG - 127          && colbase <= r + NG) ||
                  (colbase >= NN + r - 127          && colbase <= NN + r + NG) ||
                  (colbase >= 2 * NN + r - 127      && colbase <= 2 * NN + r + 1);
        } else if (band == 1) {
            hit = (colbase >= r - NG - 127          && colbase <= r) ||
                  (colbase >= NN + r - 127          && colbase <= NN + r);
        } else {
            hit = (colbase >= r - 128               && colbase <= r) ||
                  (colbase >= 2 * NN + r - 127      && colbase <= 2 * NN + r);
        }

        float4 v = z;
        if (hit)
            v = value_f4(band, r, colbase + lane * 4, c, kp, kx_in, ky_in, dk);

        ((float4*)out)[(size_t)row * F4PR + (cc << 5) + lane] = v;

        // advance
        chunk += warps_total;
        row   += d_row;
        cc    += d_cc;
        if (cc >= CHPR) { cc -= CHPR; row++; }
    }
}

extern "C" void kernel_launch(void* const* d_in, const int* in_sizes, int n_in,
                              void* d_out, int out_size)
{
    const float* c  = (const float*)d_in[0];
    const float* kp = (const float*)d_in[1];
    const float* kx = (const float*)d_in[2];
    const float* ky = (const float*)d_in[3];
    const float* dk = (const float*)d_in[4];
    float* out = (float*)d_out;

    max_kernel<<<1, 256>>>(c);
    fill_kernel<<<608, 256>>>(c, kp, kx, ky, dk, out);
}

// round 11
// speedup vs baseline: 1.1544x; 1.1412x over previous
#include <cuda_runtime.h>
#include <cstdint>

#define NG   64                 // n
#define NN   (NG * NG)          // 4096 = N
#define SDIM (3 * NN)           // 12288
#define LRF  0.001f

__device__ float g_dx;

// dx = 10 * max(c) * sqrt(2). Single block, 16KB read.
__global__ __launch_bounds__(256)
void max_kernel(const float* __restrict__ c)
{
    __shared__ float s[256];
    const float4* c4 = (const float4*)c;
    float m = 0.0f;                                  // c ~ uniform[0,1): positive
    #pragma unroll
    for (int k = 0; k < 4; k++) {
        float4 v = c4[k * 256 + threadIdx.x];
        m = fmaxf(m, fmaxf(fmaxf(v.x, v.y), fmaxf(v.z, v.w)));
    }
    s[threadIdx.x] = m;
    __syncthreads();
    #pragma unroll
    for (int st = 128; st > 0; st >>= 1) {
        if (threadIdx.x < st) s[threadIdx.x] = fmaxf(s[threadIdx.x], s[threadIdx.x + st]);
        __syncthreads();
    }
    if (threadIdx.x == 0) g_dx = 10.0f * s[0] * 1.41421356237309515f;
}

// Compute the float4 at [band-row r, cols col0..col0+3]. Executed by <=52
// threads per block, AFTER the streaming phase — register cost is off the
// hot path.
__device__ __forceinline__
float4 value_f4(int band, int r, int col0,
                const float* __restrict__ c,  const float* __restrict__ kp,
                const float* __restrict__ kx_in, const float* __restrict__ ky_in,
                const float* __restrict__ dk)
{
    const float dx = g_dx;
    const int ii = r & (NG - 1);
    const int i  = r >> 6;
    const int t  = ii * NG + i;                  // transpose-flatten index

    const bool has_pn = (r < NN - NG);
    const bool has_mn = (r >= NG);
    const bool has_p1 = (ii != NG - 1);
    const bool has_m1 = (ii != 0);

    const float cd = c[t] / dx;

    const float kxr     = kx_in[t] - LRF * dk[t];
    const float nxinv_r = 1.0f / (1.0f + kxr * 0.5f);
    const float Nxp_r   = 1.0f - kxr * 0.5f;

    const float kyr     = ky_in[t] - LRF * dk[t];
    const float nyinv_r = 1.0f / (1.0f + kyr * 0.5f);
    const float Nyp_r   = 1.0f - kyr * 0.5f;

    float c_pn = 0.f, c_mn = 0.f, c_p1 = 0.f;
    float nxinv_pn = 0.f, Nxp_pn = 0.f, nyinv_p1 = 0.f, Nyp_p1 = 0.f;
    if (has_pn) {
        c_pn = c[t + 1];
        const float kxp = kx_in[t + 1] - LRF * dk[t + 1];
        nxinv_pn = 1.0f / (1.0f + kxp * 0.5f);
        Nxp_pn   = 1.0f - kxp * 0.5f;
    }
    if (has_mn) c_mn = c[t - 1];
    if (has_p1) {
        c_p1 = c[t + NG];
        const float kyp = ky_in[t + NG] - LRF * dk[t + NG];
        nyinv_p1 = 1.0f / (1.0f + kyp * 0.5f);
        Nyp_p1   = 1.0f - kyp * 0.5f;
    }
    const float cpd = c_p1 / dx;

    float4 v = make_float4(0.f, 0.f, 0.f, 0.f);
    float* vp = (float*)&v;
    #define PUT(COL, VAL) do { int _d = (COL) - col0; \
        if ((unsigned)_d < 4u) vp[_d] = (VAL); } while (0)

    if (band == 0) {
        const float kpv  = kp[ii];
        const float minv = 1.0f / (1.0f - kpv * 0.5f);
        const float Mp   = 1.0f + kpv * 0.5f;

        float txss = -cd * cd * nxinv_r;
        if (has_pn) txss += -cd * cd * nxinv_pn;
        float tyss = -cd * cd * nyinv_r;
        if (has_p1) tyss += -cpd * cpd * nyinv_p1;

        if (has_mn) PUT(r - NG, minv * cd * (c_mn / dx) * nxinv_r);
        if (has_m1) PUT(r - 1,  minv * cd * cd * nyinv_r);
        PUT(r, minv * Mp + minv * (txss + tyss));
        if (has_p1) PUT(r + 1,  minv * cpd * cpd * nyinv_p1);
        if (has_pn) PUT(r + NG, minv * cd * (c_pn / dx) * nxinv_pn);

        PUT(NN + r, minv * cd * nxinv_r * Nxp_r);
        if (has_pn) PUT(NN + r + NG, -minv * cd * nxinv_pn * Nxp_pn);

        PUT(2 * NN + r, minv * cd * nyinv_r * Nyp_r);
        if (has_p1) PUT(2 * NN + r + 1, -minv * cpd * nyinv_p1 * Nyp_p1);
    } else if (band == 1) {
        if (has_mn) PUT(r - NG, nxinv_r * (c_mn / dx));
        PUT(r, -nxinv_r * cd);
        PUT(NN + r, nxinv_r * Nxp_r);
    } else {
        if (has_m1) PUT(r - 1, nyinv_r * cd);
        PUT(r, -nyinv_r * cd);
        PUT(2 * NN + r, nyinv_r * Nyp_r);
    }
    #undef PUT
    return v;
}

// One block per row. Phase 1: unconditional zero-stream of the whole row
// (12 x STG.128 per thread, memset-shaped). Phase 2: <=52 threads overwrite
// the row's nonzero float4s (lines still L2-resident -> no extra DRAM).
__global__ __launch_bounds__(256, 6)
void fill_kernel(const float* __restrict__ c,
                 const float* __restrict__ kp,
                 const float* __restrict__ kx_in,
                 const float* __restrict__ ky_in,
                 const float* __restrict__ dk,
                 float* __restrict__ out)
{
    const int R   = blockIdx.x;
    const int tid = threadIdx.x;
    float4* rowp  = (float4*)(out + (size_t)R * SDIM);

    // ---- phase 1: pure zero stream ----
    const float4 z = make_float4(0.f, 0.f, 0.f, 0.f);
    #pragma unroll
    for (int k = 0; k < 12; k++)
        rowp[k * 256 + tid] = z;
    __syncthreads();

    // ---- phase 2: fix-up nonzero windows ----
    int band, r;
    if (R < NN)          { band = 0; r = R; }
    else if (R < 2 * NN) { band = 1; r = R - NN; }
    else                 { band = 2; r = R - 2 * NN; }

    // float4-index windows covering every nonzero column of this row
    int w1lo, w1hi, w2lo, w2hi, w3lo = 0, c3 = 0;
    if (band == 0) {
        w1lo = max(r - NG, 0) >> 2;       w1hi = min(r + NG, NN - 1) >> 2;
        w2lo = (NN + r) >> 2;             w2hi = (NN + min(r + NG, NN - 1)) >> 2;
        w3lo = (2 * NN + r) >> 2;
        c3   = ((2 * NN + min(r + 1, NN - 1)) >> 2) - w3lo + 1;
    } else if (band == 1) {
        w1lo = max(r - NG, 0) >> 2;       w1hi = r >> 2;
        w2lo = (NN + r) >> 2;             w2hi = w2lo;
    } else {
        w1lo = max(r - 1, 0) >> 2;        w1hi = r >> 2;
        w2lo = (2 * NN + r) >> 2;         w2hi = w2lo;
    }
    const int c1 = w1hi - w1lo + 1;
    const int c2 = w2hi - w2lo + 1;

    int f4 = -1;
    if (tid < c1)                 f4 = w1lo + tid;
    else if (tid < c1 + c2)       f4 = w2lo + (tid - c1);
    else if (tid < c1 + c2 + c3)  f4 = w3lo + (tid - c1 - c2);

    if (f4 >= 0)
        rowp[f4] = value_f4(band, r, f4 * 4, c, kp, kx_in, ky_in, dk);
}

extern "C" void kernel_launch(void* const* d_in, const int* in_sizes, int n_in,
                              void* d_out, int out_size)
{
    const float* c  = (const float*)d_in[0];
    const float* kp = (const float*)d_in[1];
    const float* kx = (const float*)d_in[2];
    const float* ky = (const float*)d_in[3];
    const float* dk = (const float*)d_in[4];
    float* out = (float*)d_out;

    max_kernel<<<1, 256>>>(c);
    fill_kernel<<<SDIM, 256>>>(c, kp, kx, ky, dk, out);
}